// round 16
// baseline (speedup 1.0000x reference)
#include <cuda_runtime.h>
#include <cuda_fp16.h>
#include <cstdint>
#include <math.h>

// Problem constants (KGramMLPSeqModel: T=1024, B=4, V=32000, E=1024, K=3, H=2048)
#define T_N   1024
#define B_N   4
#define V_N   32000
#define E_N   1024
#define KCTX  3
#define H_N   2048
#define M_N   (T_N * B_N)      // 4096
#define K1_N  (KCTX * E_N)     // 3072

// ---------------------------------------------------------------------------
// Device scratch (__device__ globals per allocation-free rule)
// ---------------------------------------------------------------------------
__device__ __half g_hh[(size_t)M_N * H_N];    // h fp16 (M,H) K-major
__device__ __half g_wo[(size_t)V_N * H_N];    // Wout^T fp16 (V,H) K-major
__device__ __half g_ef[(size_t)V_N * E_N];    // embedding fp16 (V,E)
__device__ __half g_w1[(size_t)H_N * K1_N];   // W1^T fp16 (H,K1) K-major

// ---------------------------------------------------------------------------
// Helpers (baseline PTX only: plain compute_103 target)
// ---------------------------------------------------------------------------
__device__ __forceinline__ uint32_t smem_u32(const void* p) {
    uint32_t a;
    asm("{ .reg .u64 t; cvta.to.shared.u64 t, %1; cvt.u32.u64 %0, t; }" : "=r"(a) : "l"(p));
    return a;
}
#define CP16(dst, src) \
    asm volatile("cp.async.cg.shared.global [%0], [%1], 16;" :: "r"(dst), "l"(src) : "memory")
#define CP_COMMIT() asm volatile("cp.async.commit_group;" ::: "memory")
#define CP_WAIT1()  asm volatile("cp.async.wait_group 1;" ::: "memory")

#define LDSM4(r, addr) \
    asm volatile("ldmatrix.sync.aligned.m8n8.x4.shared.b16 {%0,%1,%2,%3}, [%4];" \
        : "=r"((r)[0]), "=r"((r)[1]), "=r"((r)[2]), "=r"((r)[3]) : "r"(addr))

#define MMA16816(d, a, b0, b1) \
    asm volatile("mma.sync.aligned.m16n8k16.row.col.f32.f16.f16.f32 " \
        "{%0,%1,%2,%3}, {%4,%5,%6,%7}, {%8,%9}, {%0,%1,%2,%3};" \
        : "+f"((d)[0]), "+f"((d)[1]), "+f"((d)[2]), "+f"((d)[3]) \
        : "r"((a)[0]), "r"((a)[1]), "r"((a)[2]), "r"((a)[3]), "r"(b0), "r"(b1))

// ---------------------------------------------------------------------------
// Prepass A: embedding fp32 -> fp16, same layout
// ---------------------------------------------------------------------------
__global__ __launch_bounds__(256)
void emb_convert(const float* __restrict__ emb)
{
    const size_t i4 = ((size_t)blockIdx.x * 256 + threadIdx.x) * 4;
    const float4 v = *reinterpret_cast<const float4*>(emb + i4);
    __half2* o = reinterpret_cast<__half2*>(g_ef + i4);
    o[0] = __half2(__float2half_rn(v.x), __float2half_rn(v.y));
    o[1] = __half2(__float2half_rn(v.z), __float2half_rn(v.w));
}

// ---------------------------------------------------------------------------
// Prepass B: transpose to fp16: in (R, C) fp32 -> out (C, R) fp16
// ---------------------------------------------------------------------------
__global__ __launch_bounds__(256)
void transpose_f16(const float* __restrict__ in,
                   __half* __restrict__ o,
                   int R, int C)
{
    __shared__ float tile[32][33];
    const int tx = threadIdx.x & 31;
    const int ty = threadIdx.x >> 5;          // 0..7
    const int cBase = blockIdx.x * 32;
    const int rBase = blockIdx.y * 32;

    #pragma unroll
    for (int j = 0; j < 4; j++)
        tile[ty + j * 8][tx] = in[(size_t)(rBase + ty + j * 8) * C + cBase + tx];
    __syncthreads();
    #pragma unroll
    for (int j = 0; j < 4; j++) {
        const int n = cBase + ty + j * 8;
        const int k = rBase + tx;
        o[(size_t)n * R + k] = __float2half_rn(tile[tx][ty + j * 8]);
    }
}

// ---------------------------------------------------------------------------
// Shared GEMM geometry: BM=128, BN=128, BK=64; 256 threads, 8 warps (2M x 4N),
// warp tile 64x32; single-product fp16; ROWB=144 (128B data + 16B pad, bank
// stride 36%32=4 -> conflict-free 8-row ldmatrix phases).
// 3-stage cp.async with wait_group(1): each load gets TWO compute phases of
// slack (absorbs L2 fill bursts). __launch_bounds__(256,2) -> 2 CTAs/SM
// (3 x 36864 = 110592 B/CTA; x2 = 221184 <= 227KB/SM).
// ---------------------------------------------------------------------------
#define ROWB      144
#define A_BYTES   (128 * ROWB)     // 18432
#define B_BYTES   (128 * ROWB)     // 18432
#define OFF_A     0
#define OFF_B     A_BYTES
#define STAGE_B   (A_BYTES + B_BYTES)   // 36864
#define NSTAGE    3
#define GEMM_SMEM (NSTAGE * STAGE_B)    // 110592

// One 64-k chunk, warp tile 64x32 (acc[4][4][4]); single product; 4 k16 groups.
#define COMPUTE_CHUNK(stb)                                                          \
    do {                                                                            \
        _Pragma("unroll")                                                           \
        for (int kk = 0; kk < 4; kk++) {                                            \
            const uint32_t colb = cselB + kk * 32;                                  \
            uint32_t af[4][4];                                                      \
            _Pragma("unroll")                                                       \
            for (int im = 0; im < 4; im++) {                                        \
                const uint32_t a = (stb) + OFF_A + (wm * 64 + im * 16 + rsel) * ROWB + colb; \
                LDSM4(af[im], a);                                                   \
            }                                                                       \
            uint32_t bf[2][4];                                                      \
            _Pragma("unroll")                                                       \
            for (int in = 0; in < 2; in++) {                                        \
                const uint32_t a = (stb) + OFF_B + (wn * 32 + in * 16 + rsel) * ROWB + colb; \
                LDSM4(bf[in], a);                                                   \
            }                                                                       \
            _Pragma("unroll")                                                       \
            for (int im = 0; im < 4; im++)                                          \
                _Pragma("unroll")                                                   \
                for (int jn = 0; jn < 4; jn++)                                      \
                    MMA16816(acc[im][jn], af[im], bf[jn >> 1][jn & 1], bf[jn >> 1][(jn & 1) + 2]); \
        }                                                                           \
    } while (0)

// ============================================================================
// GEMM1: h = silu(gather(emb) @ W1 + b1) -> fp16.  48 chunks of 64.
// ============================================================================
#define G1_NCHUNK (K1_N / 64)   // 48

__global__ __launch_bounds__(256, 2)
void kgram_gemm1_mma(const int* __restrict__ tokens,
                     const __half* __restrict__ ef,
                     const __half* __restrict__ w1,
                     const float* __restrict__ b1)
{
    extern __shared__ char smem[];
    const uint32_t sb = smem_u32(smem);
    const int tid  = threadIdx.x;
    const int wid  = tid >> 5;
    const int lane = tid & 31;
    const int wm   = wid >> 2;          // 0..1 (M)
    const int wn   = wid & 3;           // 0..3 (N), 32 cols each

    const int rowBase = blockIdx.x * 128;
    const int colBase = blockIdx.y * 128;

    float acc[4][4][4];
    #pragma unroll
    for (int i = 0; i < 4; i++)
        #pragma unroll
        for (int j = 0; j < 4; j++)
            #pragma unroll
            for (int e = 0; e < 4; e++) acc[i][j][e] = 0.f;

    // slot mapping: 128 rows x 8 segs of 16B; 256 threads -> 4 iters each
    const int ldRow0 = tid >> 3;        // 0..31 base row
    const int ldSeg  = tid & 7;         // 0..7
    const int segOff = ldSeg * 8;       // k-element offset within chunk

    auto load_stage = [&](int c) {
        const int c0 = c * 64;
        const uint32_t stb = sb + (c % NSTAGE) * STAGE_B;
        const int slot = c0 >> 10;          // same for all 64 k of this chunk
        const int off  = (c0 & 1023) + segOff;
        #pragma unroll
        for (int it = 0; it < 4; it++) {
            const int row = ldRow0 + it * 32;
            // A: gathered embedding
            const int r = rowBase + row;
            const int t = r >> 2;
            const int b = r & 3;
            const int tt = t - KCTX + slot;
            int tok = 0;
            if (tt >= 0) tok = tokens[tt * B_N + b];
            if (tok < 0) tok = 0;
            if (tok >= V_N) tok = V_N - 1;
            CP16(stb + row * ROWB + ldSeg * 16 + OFF_A, ef + (size_t)tok * E_N + off);
            // B: W1^T
            const size_t gB = (size_t)(colBase + row) * K1_N + c0 + segOff;
            CP16(stb + row * ROWB + ldSeg * 16 + OFF_B, w1 + gB);
        }
    };

    load_stage(0); CP_COMMIT();
    load_stage(1); CP_COMMIT();

    const int rsel  = lane & 15;
    const int cselB = (lane >> 4) * 16;

    for (int c = 0; c < G1_NCHUNK; c++) {
        CP_WAIT1();            // stage c resident (one older group may be in flight)
        __syncthreads();       // all warps done with buf (c+2)%3; stage-c data visible
        if (c + 2 < G1_NCHUNK) { load_stage(c + 2); CP_COMMIT(); }
        const uint32_t stb = sb + (c % NSTAGE) * STAGE_B;
        COMPUTE_CHUNK(stb);
    }

    // Epilogue: +b1, silu -> g_hh (fp16)
    const int mw = rowBase + wm * 64;
    const int nw = colBase + wn * 32;
    #pragma unroll
    for (int im = 0; im < 4; im++) {
        const int r0 = mw + im * 16 + (lane >> 2);
        #pragma unroll
        for (int jn = 0; jn < 4; jn++) {
            const int col = nw + jn * 8 + (lane & 3) * 2;
            const float2 bb = *reinterpret_cast<const float2*>(&b1[col]);
            float v00 = acc[im][jn][0] + bb.x;
            float v01 = acc[im][jn][1] + bb.y;
            float v10 = acc[im][jn][2] + bb.x;
            float v11 = acc[im][jn][3] + bb.y;
            v00 = v00 / (1.f + expf(-v00));
            v01 = v01 / (1.f + expf(-v01));
            v10 = v10 / (1.f + expf(-v10));
            v11 = v11 / (1.f + expf(-v11));
            *reinterpret_cast<__half2*>(g_hh + (size_t)r0 * H_N + col) =
                __half2(__float2half_rn(v00), __float2half_rn(v01));
            *reinterpret_cast<__half2*>(g_hh + (size_t)(r0 + 8) * H_N + col) =
                __half2(__float2half_rn(v10), __float2half_rn(v11));
        }
    }
}

// ============================================================================
// GEMM2: logits = h @ Wout + bout.  32 chunks of 64.
// ============================================================================
#define G2_NCHUNK (H_N / 64)    // 32

__global__ __launch_bounds__(256, 2)
void kgram_gemm2_mma(const __half* __restrict__ hh,
                     const __half* __restrict__ wo,
                     const float* __restrict__ bout,
                     float* __restrict__ out)
{
    extern __shared__ char smem[];
    const uint32_t sb = smem_u32(smem);
    const int tid  = threadIdx.x;
    const int wid  = tid >> 5;
    const int lane = tid & 31;
    const int wm   = wid >> 2;          // 0..1
    const int wn   = wid & 3;           // 0..3

    const int rowBase = blockIdx.x * 128;   // M fastest -> B-strip reuse in L2
    const int colBase = blockIdx.y * 128;

    float acc[4][4][4];
    #pragma unroll
    for (int i = 0; i < 4; i++)
        #pragma unroll
        for (int j = 0; j < 4; j++)
            #pragma unroll
            for (int e = 0; e < 4; e++) acc[i][j][e] = 0.f;

    const int ldRow0 = tid >> 3;        // 0..31
    const int ldSeg  = tid & 7;
    const int segOff = ldSeg * 8;

    auto load_stage = [&](int c) {
        const int c0 = c * 64;
        const uint32_t stb = sb + (c % NSTAGE) * STAGE_B;
        #pragma unroll
        for (int it = 0; it < 4; it++) {
            const int row = ldRow0 + it * 32;
            const uint32_t d = stb + row * ROWB + ldSeg * 16;
            CP16(d + OFF_A, hh + (size_t)(rowBase + row) * H_N + c0 + segOff);
            CP16(d + OFF_B, wo + (size_t)(colBase + row) * H_N + c0 + segOff);
        }
    };

    load_stage(0); CP_COMMIT();
    load_stage(1); CP_COMMIT();

    const int rsel  = lane & 15;
    const int cselB = (lane >> 4) * 16;

    for (int c = 0; c < G2_NCHUNK; c++) {
        CP_WAIT1();
        __syncthreads();
        if (c + 2 < G2_NCHUNK) { load_stage(c + 2); CP_COMMIT(); }
        const uint32_t stb = sb + (c % NSTAGE) * STAGE_B;
        COMPUTE_CHUNK(stb);
    }

    // Epilogue: +bout -> gmem
    const int mw = rowBase + wm * 64;
    const int nw = colBase + wn * 32;
    #pragma unroll
    for (int im = 0; im < 4; im++) {
        const int r0 = mw + im * 16 + (lane >> 2);
        #pragma unroll
        for (int jn = 0; jn < 4; jn++) {
            const int col = nw + jn * 8 + (lane & 3) * 2;
            const float2 bb = *reinterpret_cast<const float2*>(&bout[col]);
            float2 o0, o1;
            o0.x = acc[im][jn][0] + bb.x;
            o0.y = acc[im][jn][1] + bb.y;
            o1.x = acc[im][jn][2] + bb.x;
            o1.y = acc[im][jn][3] + bb.y;
            *reinterpret_cast<float2*>(&out[(size_t)r0 * V_N + col])       = o0;
            *reinterpret_cast<float2*>(&out[(size_t)(r0 + 8) * V_N + col]) = o1;
        }
    }
}

// ---------------------------------------------------------------------------
// Launch
// ---------------------------------------------------------------------------
extern "C" void kernel_launch(void* const* d_in, const int* in_sizes, int n_in,
                              void* d_out, int out_size)
{
    const int*   tokens = (const int*)d_in[0];     // (T, B) int32
    const float* emb    = (const float*)d_in[1];   // (V, E)
    const float* W1     = (const float*)d_in[2];   // (K*E, H)
    const float* b1     = (const float*)d_in[3];   // (H,)
    const float* Wout   = (const float*)d_in[4];   // (H, V)
    const float* bout   = (const float*)d_in[5];   // (V,)
    float*       out    = (float*)d_out;           // (T, B, V) fp32

    __half *hh, *wo, *ef, *w1;
    cudaGetSymbolAddress((void**)&hh, g_hh);
    cudaGetSymbolAddress((void**)&wo, g_wo);
    cudaGetSymbolAddress((void**)&ef, g_ef);
    cudaGetSymbolAddress((void**)&w1, g_w1);

    // Prepasses
    emb_convert<<<(int)(((size_t)V_N * E_N) / 1024), 256>>>(emb);
    transpose_f16<<<dim3(H_N / 32, K1_N / 32), 256>>>(W1, w1, K1_N, H_N);
    transpose_f16<<<dim3(V_N / 32, H_N / 32), 256>>>(Wout, wo, H_N, V_N);

    // GEMM1 (fp16 1-product, gathered A) -> h fp16
    cudaFuncSetAttribute(kgram_gemm1_mma, cudaFuncAttributeMaxDynamicSharedMemorySize, GEMM_SMEM);
    kgram_gemm1_mma<<<dim3(M_N / 128, H_N / 128), 256, GEMM_SMEM>>>(tokens, ef, w1, b1);

    // GEMM2 (fp16 1-product)
    cudaFuncSetAttribute(kgram_gemm2_mma, cudaFuncAttributeMaxDynamicSharedMemorySize, GEMM_SMEM);
    kgram_gemm2_mma<<<dim3(M_N / 128, V_N / 128), 256, GEMM_SMEM>>>(hh, wo, bout, out);
}

// round 17
// speedup vs baseline: 1.0490x; 1.0490x over previous
#include <cuda_runtime.h>
#include <cuda_fp16.h>
#include <cstdint>
#include <math.h>

// Problem constants (KGramMLPSeqModel: T=1024, B=4, V=32000, E=1024, K=3, H=2048)
#define T_N   1024
#define B_N   4
#define V_N   32000
#define E_N   1024
#define KCTX  3
#define H_N   2048
#define M_N   (T_N * B_N)      // 4096
#define K1_N  (KCTX * E_N)     // 3072

// ---------------------------------------------------------------------------
// Device scratch (__device__ globals per allocation-free rule)
// ---------------------------------------------------------------------------
__device__ __half g_hh[(size_t)M_N * H_N];    // h fp16 (M,H) K-major
__device__ __half g_wo[(size_t)V_N * H_N];    // Wout^T fp16 (V,H) K-major
__device__ __half g_ef[(size_t)V_N * E_N];    // embedding fp16 (V,E)
__device__ __half g_w1[(size_t)H_N * K1_N];   // W1^T fp16 (H,K1) K-major

// ---------------------------------------------------------------------------
// Helpers (baseline PTX only: plain compute_103 target)
// ---------------------------------------------------------------------------
__device__ __forceinline__ uint32_t smem_u32(const void* p) {
    uint32_t a;
    asm("{ .reg .u64 t; cvta.to.shared.u64 t, %1; cvt.u32.u64 %0, t; }" : "=r"(a) : "l"(p));
    return a;
}
#define CP16(dst, src) \
    asm volatile("cp.async.cg.shared.global [%0], [%1], 16;" :: "r"(dst), "l"(src) : "memory")
#define CP_COMMIT() asm volatile("cp.async.commit_group;" ::: "memory")
#define CP_WAIT0()  asm volatile("cp.async.wait_group 0;" ::: "memory")

#define LDSM4(r, addr) \
    asm volatile("ldmatrix.sync.aligned.m8n8.x4.shared.b16 {%0,%1,%2,%3}, [%4];" \
        : "=r"((r)[0]), "=r"((r)[1]), "=r"((r)[2]), "=r"((r)[3]) : "r"(addr))

#define MMA16816(d, a, b0, b1) \
    asm volatile("mma.sync.aligned.m16n8k16.row.col.f32.f16.f16.f32 " \
        "{%0,%1,%2,%3}, {%4,%5,%6,%7}, {%8,%9}, {%0,%1,%2,%3};" \
        : "+f"((d)[0]), "+f"((d)[1]), "+f"((d)[2]), "+f"((d)[3]) \
        : "r"((a)[0]), "r"((a)[1]), "r"((a)[2]), "r"((a)[3]), "r"(b0), "r"(b1))

// ---------------------------------------------------------------------------
// Prepass A: embedding fp32 -> fp16, same layout
// ---------------------------------------------------------------------------
__global__ __launch_bounds__(256)
void emb_convert(const float* __restrict__ emb)
{
    const size_t i4 = ((size_t)blockIdx.x * 256 + threadIdx.x) * 4;
    const float4 v = *reinterpret_cast<const float4*>(emb + i4);
    __half2* o = reinterpret_cast<__half2*>(g_ef + i4);
    o[0] = __half2(__float2half_rn(v.x), __float2half_rn(v.y));
    o[1] = __half2(__float2half_rn(v.z), __float2half_rn(v.w));
}

// ---------------------------------------------------------------------------
// Prepass B: transpose to fp16: in (R, C) fp32 -> out (C, R) fp16
// ---------------------------------------------------------------------------
__global__ __launch_bounds__(256)
void transpose_f16(const float* __restrict__ in,
                   __half* __restrict__ o,
                   int R, int C)
{
    __shared__ float tile[32][33];
    const int tx = threadIdx.x & 31;
    const int ty = threadIdx.x >> 5;          // 0..7
    const int cBase = blockIdx.x * 32;
    const int rBase = blockIdx.y * 32;

    #pragma unroll
    for (int j = 0; j < 4; j++)
        tile[ty + j * 8][tx] = in[(size_t)(rBase + ty + j * 8) * C + cBase + tx];
    __syncthreads();
    #pragma unroll
    for (int j = 0; j < 4; j++) {
        const int n = cBase + ty + j * 8;
        const int k = rBase + tx;
        o[(size_t)n * R + k] = __float2half_rn(tile[tx][ty + j * 8]);
    }
}

// ---------------------------------------------------------------------------
// Shared GEMM geometry: BM=128, BN=128, BK=64; 256 threads, 8 warps (2M x 4N),
// warp tile 64x32; single-product fp16; ROWB=144 (128B data + 16B pad, bank
// stride 36%32=4 -> conflict-free 8-row ldmatrix phases).
// 2-stage cp.async (R15 proven best); __launch_bounds__(256,2) -> 2 CTAs/SM.
// COMPUTE_CHUNK hoists LDSM base addresses: each LDSM = base + immediate.
// ---------------------------------------------------------------------------
#define ROWB      144
#define A_BYTES   (128 * ROWB)     // 18432
#define B_BYTES   (128 * ROWB)     // 18432
#define OFF_A     0
#define OFF_B     A_BYTES
#define STAGE_B   (A_BYTES + B_BYTES)   // 36864
#define NSTAGE    2
#define GEMM_SMEM (NSTAGE * STAGE_B)    // 73728 (x2 CTAs = 147KB <= 227KB)

// One 64-k chunk, warp tile 64x32 (acc[4][4][4]); single product; 4 k16 groups.
// aW/bW are per-thread constants hoisted by the caller:
//   aW = (wm*64 + rsel)*ROWB + cselB,  bW = (wn*32 + rsel)*ROWB + cselB
// All loop-varying terms are compile-time immediates.
#define COMPUTE_CHUNK(stb)                                                          \
    do {                                                                            \
        const uint32_t aBase = (stb) + OFF_A + aW;                                  \
        const uint32_t bBase = (stb) + OFF_B + bW;                                  \
        _Pragma("unroll")                                                           \
        for (int kk = 0; kk < 4; kk++) {                                            \
            uint32_t af[4][4];                                                      \
            _Pragma("unroll")                                                       \
            for (int im = 0; im < 4; im++)                                          \
                LDSM4(af[im], aBase + im * (16 * ROWB) + kk * 32);                  \
            uint32_t bf[2][4];                                                      \
            _Pragma("unroll")                                                       \
            for (int in = 0; in < 2; in++)                                          \
                LDSM4(bf[in], bBase + in * (16 * ROWB) + kk * 32);                  \
            _Pragma("unroll")                                                       \
            for (int im = 0; im < 4; im++)                                          \
                _Pragma("unroll")                                                   \
                for (int jn = 0; jn < 4; jn++)                                      \
                    MMA16816(acc[im][jn], af[im], bf[jn >> 1][jn & 1], bf[jn >> 1][(jn & 1) + 2]); \
        }                                                                           \
    } while (0)

// ============================================================================
// GEMM1: h = silu(gather(emb) @ W1 + b1) -> fp16.  48 chunks of 64.
// ============================================================================
#define G1_NCHUNK (K1_N / 64)   // 48

__global__ __launch_bounds__(256, 2)
void kgram_gemm1_mma(const int* __restrict__ tokens,
                     const __half* __restrict__ ef,
                     const __half* __restrict__ w1,
                     const float* __restrict__ b1)
{
    extern __shared__ char smem[];
    const uint32_t sb = smem_u32(smem);
    const int tid  = threadIdx.x;
    const int wid  = tid >> 5;
    const int lane = tid & 31;
    const int wm   = wid >> 2;          // 0..1 (M)
    const int wn   = wid & 3;           // 0..3 (N), 32 cols each

    const int rowBase = blockIdx.x * 128;
    const int colBase = blockIdx.y * 128;

    float acc[4][4][4];
    #pragma unroll
    for (int i = 0; i < 4; i++)
        #pragma unroll
        for (int j = 0; j < 4; j++)
            #pragma unroll
            for (int e = 0; e < 4; e++) acc[i][j][e] = 0.f;

    // slot mapping: 128 rows x 8 segs of 16B; 256 threads -> 4 iters each
    const int ldRow0 = tid >> 3;        // 0..31 base row
    const int ldSeg  = tid & 7;         // 0..7
    const int segOff = ldSeg * 8;       // k-element offset within chunk
    const uint32_t dOff = ldRow0 * ROWB + ldSeg * 16;

    // Precomputed W1 global bases (advance by +c*64 per chunk)
    const __half* w1b0 = w1 + (size_t)(colBase + ldRow0)      * K1_N + segOff;
    const __half* w1b1 = w1 + (size_t)(colBase + ldRow0 + 32) * K1_N + segOff;
    const __half* w1b2 = w1 + (size_t)(colBase + ldRow0 + 64) * K1_N + segOff;
    const __half* w1b3 = w1 + (size_t)(colBase + ldRow0 + 96) * K1_N + segOff;

    auto load_stage = [&](int c) {
        const int c0 = c * 64;
        const uint32_t stb = sb + (c & 1) * STAGE_B;
        const int slot = c0 >> 10;          // same for all 64 k of this chunk
        const int off  = (c0 & 1023) + segOff;
        #pragma unroll
        for (int it = 0; it < 4; it++) {
            const int row = ldRow0 + it * 32;
            // A: gathered embedding
            const int r = rowBase + row;
            const int t = r >> 2;
            const int b = r & 3;
            const int tt = t - KCTX + slot;
            int tok = 0;
            if (tt >= 0) tok = tokens[tt * B_N + b];
            if (tok < 0) tok = 0;
            if (tok >= V_N) tok = V_N - 1;
            CP16(stb + dOff + it * (32 * ROWB) + OFF_A, ef + (size_t)tok * E_N + off);
        }
        // B: W1^T (precomputed bases)
        CP16(stb + dOff + 0 * (32 * ROWB) + OFF_B, w1b0 + c0);
        CP16(stb + dOff + 1 * (32 * ROWB) + OFF_B, w1b1 + c0);
        CP16(stb + dOff + 2 * (32 * ROWB) + OFF_B, w1b2 + c0);
        CP16(stb + dOff + 3 * (32 * ROWB) + OFF_B, w1b3 + c0);
    };

    load_stage(0); CP_COMMIT();

    const int rsel  = lane & 15;
    const int cselB = (lane >> 4) * 16;
    const uint32_t aW = (wm * 64 + rsel) * ROWB + cselB;
    const uint32_t bW = (wn * 32 + rsel) * ROWB + cselB;

    for (int c = 0; c < G1_NCHUNK; c++) {
        CP_WAIT0();            // stage c resident (this thread's groups)
        __syncthreads();       // all warps done with compute(c-1); data visible
        if (c + 1 < G1_NCHUNK) { load_stage(c + 1); CP_COMMIT(); }
        const uint32_t stb = sb + (c & 1) * STAGE_B;
        COMPUTE_CHUNK(stb);
    }

    // Epilogue: +b1, silu -> g_hh (fp16)
    const int mw = rowBase + wm * 64;
    const int nw = colBase + wn * 32;
    #pragma unroll
    for (int im = 0; im < 4; im++) {
        const int r0 = mw + im * 16 + (lane >> 2);
        #pragma unroll
        for (int jn = 0; jn < 4; jn++) {
            const int col = nw + jn * 8 + (lane & 3) * 2;
            const float2 bb = *reinterpret_cast<const float2*>(&b1[col]);
            float v00 = acc[im][jn][0] + bb.x;
            float v01 = acc[im][jn][1] + bb.y;
            float v10 = acc[im][jn][2] + bb.x;
            float v11 = acc[im][jn][3] + bb.y;
            v00 = v00 / (1.f + expf(-v00));
            v01 = v01 / (1.f + expf(-v01));
            v10 = v10 / (1.f + expf(-v10));
            v11 = v11 / (1.f + expf(-v11));
            *reinterpret_cast<__half2*>(g_hh + (size_t)r0 * H_N + col) =
                __half2(__float2half_rn(v00), __float2half_rn(v01));
            *reinterpret_cast<__half2*>(g_hh + (size_t)(r0 + 8) * H_N + col) =
                __half2(__float2half_rn(v10), __float2half_rn(v11));
        }
    }
}

// ============================================================================
// GEMM2: logits = h @ Wout + bout.  32 chunks of 64.
// ============================================================================
#define G2_NCHUNK (H_N / 64)    // 32

__global__ __launch_bounds__(256, 2)
void kgram_gemm2_mma(const __half* __restrict__ hh,
                     const __half* __restrict__ wo,
                     const float* __restrict__ bout,
                     float* __restrict__ out)
{
    extern __shared__ char smem[];
    const uint32_t sb = smem_u32(smem);
    const int tid  = threadIdx.x;
    const int wid  = tid >> 5;
    const int lane = tid & 31;
    const int wm   = wid >> 2;          // 0..1
    const int wn   = wid & 3;           // 0..3

    const int rowBase = blockIdx.x * 128;   // M fastest -> B-strip reuse in L2
    const int colBase = blockIdx.y * 128;

    float acc[4][4][4];
    #pragma unroll
    for (int i = 0; i < 4; i++)
        #pragma unroll
        for (int j = 0; j < 4; j++)
            #pragma unroll
            for (int e = 0; e < 4; e++) acc[i][j][e] = 0.f;

    const int ldRow0 = tid >> 3;        // 0..31
    const int ldSeg  = tid & 7;
    const int segOff = ldSeg * 8;
    const uint32_t dOff = ldRow0 * ROWB + ldSeg * 16;

    // Precomputed global bases (advance by +c*64 per chunk)
    const __half* hA0 = hh + (size_t)(rowBase + ldRow0)      * H_N + segOff;
    const __half* hA1 = hh + (size_t)(rowBase + ldRow0 + 32) * H_N + segOff;
    const __half* hA2 = hh + (size_t)(rowBase + ldRow0 + 64) * H_N + segOff;
    const __half* hA3 = hh + (size_t)(rowBase + ldRow0 + 96) * H_N + segOff;
    const __half* wB0 = wo + (size_t)(colBase + ldRow0)      * H_N + segOff;
    const __half* wB1 = wo + (size_t)(colBase + ldRow0 + 32) * H_N + segOff;
    const __half* wB2 = wo + (size_t)(colBase + ldRow0 + 64) * H_N + segOff;
    const __half* wB3 = wo + (size_t)(colBase + ldRow0 + 96) * H_N + segOff;

    auto load_stage = [&](int c) {
        const int c0 = c * 64;
        const uint32_t stb = sb + (c & 1) * STAGE_B;
        CP16(stb + dOff + 0 * (32 * ROWB) + OFF_A, hA0 + c0);
        CP16(stb + dOff + 1 * (32 * ROWB) + OFF_A, hA1 + c0);
        CP16(stb + dOff + 2 * (32 * ROWB) + OFF_A, hA2 + c0);
        CP16(stb + dOff + 3 * (32 * ROWB) + OFF_A, hA3 + c0);
        CP16(stb + dOff + 0 * (32 * ROWB) + OFF_B, wB0 + c0);
        CP16(stb + dOff + 1 * (32 * ROWB) + OFF_B, wB1 + c0);
        CP16(stb + dOff + 2 * (32 * ROWB) + OFF_B, wB2 + c0);
        CP16(stb + dOff + 3 * (32 * ROWB) + OFF_B, wB3 + c0);
    };

    load_stage(0); CP_COMMIT();

    const int rsel  = lane & 15;
    const int cselB = (lane >> 4) * 16;
    const uint32_t aW = (wm * 64 + rsel) * ROWB + cselB;
    const uint32_t bW = (wn * 32 + rsel) * ROWB + cselB;

    for (int c = 0; c < G2_NCHUNK; c++) {
        CP_WAIT0();
        __syncthreads();
        if (c + 1 < G2_NCHUNK) { load_stage(c + 1); CP_COMMIT(); }
        const uint32_t stb = sb + (c & 1) * STAGE_B;
        COMPUTE_CHUNK(stb);
    }

    // Epilogue: +bout -> gmem
    const int mw = rowBase + wm * 64;
    const int nw = colBase + wn * 32;
    #pragma unroll
    for (int im = 0; im < 4; im++) {
        const int r0 = mw + im * 16 + (lane >> 2);
        #pragma unroll
        for (int jn = 0; jn < 4; jn++) {
            const int col = nw + jn * 8 + (lane & 3) * 2;
            const float2 bb = *reinterpret_cast<const float2*>(&bout[col]);
            float2 o0, o1;
            o0.x = acc[im][jn][0] + bb.x;
            o0.y = acc[im][jn][1] + bb.y;
            o1.x = acc[im][jn][2] + bb.x;
            o1.y = acc[im][jn][3] + bb.y;
            *reinterpret_cast<float2*>(&out[(size_t)r0 * V_N + col])       = o0;
            *reinterpret_cast<float2*>(&out[(size_t)(r0 + 8) * V_N + col]) = o1;
        }
    }
}

// ---------------------------------------------------------------------------
// Launch
// ---------------------------------------------------------------------------
extern "C" void kernel_launch(void* const* d_in, const int* in_sizes, int n_in,
                              void* d_out, int out_size)
{
    const int*   tokens = (const int*)d_in[0];     // (T, B) int32
    const float* emb    = (const float*)d_in[1];   // (V, E)
    const float* W1     = (const float*)d_in[2];   // (K*E, H)
    const float* b1     = (const float*)d_in[3];   // (H,)
    const float* Wout   = (const float*)d_in[4];   // (H, V)
    const float* bout   = (const float*)d_in[5];   // (V,)
    float*       out    = (float*)d_out;           // (T, B, V) fp32

    __half *hh, *wo, *ef, *w1;
    cudaGetSymbolAddress((void**)&hh, g_hh);
    cudaGetSymbolAddress((void**)&wo, g_wo);
    cudaGetSymbolAddress((void**)&ef, g_ef);
    cudaGetSymbolAddress((void**)&w1, g_w1);

    // Prepasses
    emb_convert<<<(int)(((size_t)V_N * E_N) / 1024), 256>>>(emb);
    transpose_f16<<<dim3(H_N / 32, K1_N / 32), 256>>>(W1, w1, K1_N, H_N);
    transpose_f16<<<dim3(V_N / 32, H_N / 32), 256>>>(Wout, wo, H_N, V_N);

    // GEMM1 (fp16 1-product, gathered A) -> h fp16
    cudaFuncSetAttribute(kgram_gemm1_mma, cudaFuncAttributeMaxDynamicSharedMemorySize, GEMM_SMEM);
    kgram_gemm1_mma<<<dim3(M_N / 128, H_N / 128), 256, GEMM_SMEM>>>(tokens, ef, w1, b1);

    // GEMM2 (fp16 1-product)
    cudaFuncSetAttribute(kgram_gemm2_mma, cudaFuncAttributeMaxDynamicSharedMemorySize, GEMM_SMEM);
    kgram_gemm2_mma<<<dim3(M_N / 128, V_N / 128), 256, GEMM_SMEM>>>(hh, wo, bout, out);
}